// round 2
// baseline (speedup 1.0000x reference)
#include <cuda_runtime.h>

#define VS 100
#define BATCH 8
#define NUM_COORDS 65536
#define NPTS (BATCH * NUM_COORDS)          // 524288
#define NCELLS (BATCH * VS * VS * VS)      // 8,000,000

// Scratch: zero-initialized at module load; every launch leaves it zeroed
// (finalize zeroes exactly the cells that were occupied), so graph replays
// are deterministic without an explicit clear pass.
__device__ float g_sum[(size_t)NCELLS * 8];  // 256 MB; ch0..5 = sums, ch6 = count
__device__ float g_cnt[NCELLS];              // 32 MB compact count, coalesced scan

__global__ void __launch_bounds__(256) scatter_kernel(
    const float* __restrict__ coords,
    const float* __restrict__ feats)
{
    int idx = blockIdx.x * blockDim.x + threadIdx.x;
    if (idx >= NPTS) return;

    float x = coords[idx * 3 + 0];
    float y = coords[idx * 3 + 1];
    float z = coords[idx * 3 + 2];

    // Reference constants collapse in f32: res = denom = 0.01f, mins_shifted = -0.01f
    const float shift = 0.01f;
    const float denom = 0.01f;
    int ix = (int)floorf((x + shift) / denom);
    int iy = (int)floorf((y + shift) / denom);
    int iz = (int)floorf((z + shift) / denom);

    // Indices outside [1,VS] land in the halo the reference slices away.
    if (ix < 1 || ix > VS || iy < 1 || iy > VS || iz < 1 || iz > VS) return;

    int b = idx >> 16;  // NUM_COORDS = 65536
    int cell = ((b * VS + (ix - 1)) * VS + (iy - 1)) * VS + (iz - 1);

    float f0 = feats[idx * 3 + 0];
    float f1 = feats[idx * 3 + 1];
    float f2 = feats[idx * 3 + 2];

    float* s = &g_sum[(size_t)cell * 8];
    atomicAdd(s + 0, x);
    atomicAdd(s + 1, y);
    atomicAdd(s + 2, z);
    atomicAdd(s + 3, f0);
    atomicAdd(s + 4, f1);
    atomicAdd(s + 5, f2);
    atomicAdd(&g_cnt[cell], 1.0f);
}

__global__ void __launch_bounds__(256) finalize_kernel(float* __restrict__ out)
{
    __shared__ float stage[256 * 10];  // 10 KB

    int cell = blockIdx.x * 256 + threadIdx.x;  // grid sized exactly to NCELLS

    // Decode cell -> (i, j, k) within the batch's 100^3 block.
    int k = cell % VS;
    int t = cell / VS;
    int j = t % VS;
    t /= VS;
    int i = t % VS;

    float cnt = g_cnt[cell];

    float v0 = 0.f, v1 = 0.f, v2 = 0.f, v3 = 0.f, v4 = 0.f, v5 = 0.f, occ = 0.f;
    if (cnt > 0.0f) {
        float4* sp = (float4*)&g_sum[(size_t)cell * 8];
        float4 a = sp[0];
        float4 b4 = sp[1];
        v0 = a.x / cnt;
        v1 = a.y / cnt;
        v2 = a.z / cnt;
        v3 = a.w / cnt;
        v4 = b4.x / cnt;
        v5 = b4.y / cnt;
        occ = 1.0f;
        // Self-clean scratch for the next graph replay.
        float4 z4 = make_float4(0.f, 0.f, 0.f, 0.f);
        sp[0] = z4;
        sp[1] = z4;
        g_cnt[cell] = 0.0f;
    }

    int base = threadIdx.x * 10;
    stage[base + 0] = v0;
    stage[base + 1] = v1;
    stage[base + 2] = v2;
    stage[base + 3] = v3;
    stage[base + 4] = v4;
    stage[base + 5] = v5;
    stage[base + 6] = (float)i * 0.01f;
    stage[base + 7] = (float)j * 0.01f;
    stage[base + 8] = (float)k * 0.01f;
    stage[base + 9] = occ;
    __syncthreads();

    // 256 cells * 10 f32 = 640 float4, fully coalesced.
    float4* o4 = (float4*)(out + (size_t)blockIdx.x * 2560);
    const float4* s4 = (const float4*)stage;
#pragma unroll
    for (int w = threadIdx.x; w < 640; w += 256) {
        o4[w] = s4[w];
    }
}

extern "C" void kernel_launch(void* const* d_in, const int* in_sizes, int n_in,
                              void* d_out, int out_size)
{
    const float* coords = (const float*)d_in[0];
    const float* feats  = (const float*)d_in[1];
    float* out = (float*)d_out;

    scatter_kernel<<<(NPTS + 255) / 256, 256>>>(coords, feats);
    finalize_kernel<<<NCELLS / 256, 256>>>(out);  // 31250 blocks
}